// round 1
// baseline (speedup 1.0000x reference)
#include <cuda_runtime.h>

// RadarNet: per-row pipeline
//   x(8192,512) -> sliding-window covariance C(20,20) -> S1=W1^T C W1 (16x16)
//   -> ReEig (eigh, clamp ev at 1e-4, reconstruct)  [skipped via certified
//      Gershgorin bound when no eigenvalue can be below 1e-4 -- exact identity]
//   -> S2=W2^T S1r W2 (8x8) -> LogEig (eigh, log ev, reconstruct)
//   -> flatten(64) @ Wlin^T + blin -> out(8192,3)

namespace {
constexpr int   TLEN = 512;
constexpr int   WINW = 20;
constexpr int   NW   = 493;           // (512-20)/1 + 1
constexpr int   D1   = 16;
constexpr int   D2   = 8;
constexpr float REEPS = 1e-4f;
}

__global__ __launch_bounds__(256)
void radarnet_kernel(const float* __restrict__ gx,
                     const float* __restrict__ gW1,
                     const float* __restrict__ gW2,
                     const float* __restrict__ gWl,
                     const float* __restrict__ gbl,
                     float* __restrict__ out)
{
    __shared__ __align__(16) float xs[544];     // 512 + zero pad
    __shared__ float w1s[WINW * D1];            // W1 row-major (20,16)
    __shared__ float w2s[D1 * D2];              // W2 row-major (16,8)
    __shared__ float wls[3 * D2 * D2];          // Wlin (3,64)
    __shared__ float bls[3];
    __shared__ float Cm[WINW][WINW + 1];
    __shared__ float Tm[WINW][D1];
    __shared__ float Am[D1][D1 + 1];
    __shared__ float Vm[D1][D1 + 1];
    __shared__ float Rm[D1][D1 + 1];
    __shared__ float T2[D1][D2];
    __shared__ float A8[D2][D2 + 1];
    __shared__ float V8[D2][D2 + 1];
    __shared__ float Lf[D2 * D2];
    __shared__ float lagw[4][21];
    __shared__ float lag[21];
    __shared__ float mw[WINW];
    __shared__ float al[D1], be[D1];
    __shared__ int   pr[D1];
    __shared__ float gsh[D1];
    __shared__ float redw[8];
    __shared__ float lg8[D2];
    __shared__ int   sflag, cflag;

    const int tid = threadIdx.x;
    const int b   = blockIdx.x;

    // ---------------- load row + weights ----------------
    xs[tid]        = gx[b * TLEN + tid];
    xs[256 + tid]  = gx[b * TLEN + 256 + tid];
    if (tid < 32) xs[512 + tid] = 0.f;
    for (int i = tid; i < WINW * D1; i += 256) w1s[i] = gW1[i];
    if (tid < D1 * D2) w2s[tid] = gW2[tid];
    if (tid < 3 * D2 * D2) wls[tid] = gWl[tid];
    if (tid < 3) bls[tid] = gbl[tid];
    __syncthreads();

    // ---------------- base lag sums: lag[d] = sum_n xs[n]*xs[n+d], n<493 ----
    float acc[21];
    #pragma unroll
    for (int d = 0; d < 21; ++d) acc[d] = 0.f;
    if (tid < 124) {
        const float4* x4 = reinterpret_cast<const float4*>(xs);
        float xv[24];
        #pragma unroll
        for (int q = 0; q < 6; ++q) {
            float4 v = x4[tid + q];
            xv[4*q+0] = v.x; xv[4*q+1] = v.y; xv[4*q+2] = v.z; xv[4*q+3] = v.w;
        }
        #pragma unroll
        for (int k = 0; k < 4; ++k) {
            if (4 * tid + k <= NW - 1) {
                float xk = xv[k];
                #pragma unroll
                for (int d = 0; d < WINW; ++d) acc[d] = fmaf(xk, xv[k + d], acc[d]);
                acc[20] += xk;          // linear sum for means
            }
        }
    }
    if (tid < 128) {
        #pragma unroll
        for (int d = 0; d < 21; ++d) {
            float v = acc[d];
            #pragma unroll
            for (int o = 16; o; o >>= 1) v += __shfl_down_sync(0xffffffffu, v, o);
            if ((tid & 31) == 0) lagw[tid >> 5][d] = v;
        }
    }
    __syncthreads();
    if (tid < 21) lag[tid] = lagw[0][tid] + lagw[1][tid] + lagw[2][tid] + lagw[3][tid];
    __syncthreads();

    // per-position window means m[w] = (1/N) sum_n xs[n+w]
    if (tid == 0) {
        float ms = lag[20];
        mw[0] = ms * (1.f / (float)NW);
        for (int w = 1; w < WINW; ++w) {
            ms += xs[w - 1 + NW] - xs[w - 1];
            mw[w] = ms * (1.f / (float)NW);
        }
    }
    __syncthreads();

    // C via diagonal recurrence: S(w+1,v+1) = S(w,v) - x[w]x[v] + x[493+w]x[493+v]
    if (tid < WINW) {
        const int d = tid;
        const float inv = 1.f / (float)(NW - 1);
        float s = lag[d];
        float cv = (s - (float)NW * mw[0] * mw[d]) * inv;
        Cm[0][d] = cv; Cm[d][0] = cv;
        for (int w = 1; w + d < WINW; ++w) {
            s += xs[NW - 1 + w] * xs[NW - 1 + w + d] - xs[w - 1] * xs[w - 1 + d];
            cv = (s - (float)NW * mw[w] * mw[w + d]) * inv;
            Cm[w][w + d] = cv; Cm[w + d][w] = cv;
        }
    }
    __syncthreads();

    // ---------------- S1 = W1^T C W1 ----------------
    for (int idx = tid; idx < WINW * D1; idx += 256) {
        int w = idx >> 4, j = idx & 15;
        float s = 0.f;
        #pragma unroll
        for (int v = 0; v < WINW; ++v) s += Cm[w][v] * w1s[v * D1 + j];
        Tm[w][j] = s;
    }
    __syncthreads();
    const int i16 = tid >> 4, j16 = tid & 15;
    {
        float s = 0.f;
        #pragma unroll
        for (int w = 0; w < WINW; ++w) s += w1s[w * D1 + i16] * Tm[w][j16];
        Am[i16][j16] = s;
    }
    __syncthreads();

    // ---------------- ReEig: certified skip via Gershgorin ----------------
    if (tid < D1) {
        float r = 0.f;
        #pragma unroll
        for (int j = 0; j < D1; ++j) if (j != tid) r += fabsf(Am[tid][j]);
        gsh[tid] = Am[tid][tid] - r;
    }
    __syncthreads();
    if (tid == 0) {
        float bmin = gsh[0];
        #pragma unroll
        for (int i = 1; i < D1; ++i) bmin = fminf(bmin, gsh[i]);
        sflag = (bmin >= REEPS) ? 0 : 1;   // bound >= eps  =>  clamp is a no-op
    }
    __syncthreads();

    if (sflag == 0) {
        Rm[i16][j16] = Am[i16][j16];       // exact: U max(ev,eps) U^T == S1
    } else {
        // full 16x16 parallel cyclic Jacobi (rare path)
        Vm[i16][j16] = (i16 == j16) ? 1.f : 0.f;
        __syncthreads();
        for (int sweep = 0; sweep < 10; ++sweep) {
            for (int r = 0; r < 15; ++r) {
                if (tid < 8) {
                    int k = tid;
                    int sa = (k == 0) ? 0 : ((k - 1 + r) % 15) + 1;
                    int sb = ((14 - k + r) % 15) + 1;
                    int p = sa < sb ? sa : sb;
                    int q = sa < sb ? sb : sa;
                    float app = Am[p][p], aqq = Am[q][q], apq = Am[p][q];
                    float c, s;
                    if (fabsf(apq) < 1e-12f) { c = 1.f; s = 0.f; }
                    else {
                        float th = (aqq - app) / (2.f * apq);
                        float t = 1.f / (fabsf(th) + sqrtf(fmaf(th, th, 1.f)));
                        if (th < 0.f) t = -t;
                        c = rsqrtf(fmaf(t, t, 1.f)); s = t * c;
                    }
                    al[p] = c; be[p] = -s; pr[p] = q;
                    al[q] = c; be[q] =  s; pr[q] = p;
                }
                __syncthreads();
                float aij = Am[i16][j16], apj = Am[pr[i16]][j16];
                __syncthreads();
                Am[i16][j16] = al[i16] * aij + be[i16] * apj;
                __syncthreads();
                float bij = Am[i16][j16], bip = Am[i16][pr[j16]];
                float vij = Vm[i16][j16], vip = Vm[i16][pr[j16]];
                __syncthreads();
                Am[i16][j16] = al[j16] * bij + be[j16] * bip;
                Vm[i16][j16] = al[j16] * vij + be[j16] * vip;
                __syncthreads();
            }
            float sq = (i16 != j16) ? Am[i16][j16] * Am[i16][j16] : 0.f;
            #pragma unroll
            for (int o = 16; o; o >>= 1) sq += __shfl_down_sync(0xffffffffu, sq, o);
            if ((tid & 31) == 0) redw[tid >> 5] = sq;
            __syncthreads();
            if (tid == 0) {
                float t = 0.f;
                #pragma unroll
                for (int w = 0; w < 8; ++w) t += redw[w];
                cflag = (t < 1e-10f) ? 1 : 0;
            }
            __syncthreads();
            if (cflag) break;
        }
        float s = 0.f;
        #pragma unroll
        for (int k = 0; k < D1; ++k)
            s += Vm[i16][k] * fmaxf(Am[k][k], REEPS) * Vm[j16][k];
        Rm[i16][j16] = s;
    }
    __syncthreads();

    // ---------------- S2 = W2^T S1r W2 ----------------
    if (tid < D1 * D2) {
        int i = tid >> 3, c = tid & 7;
        float s = 0.f;
        #pragma unroll
        for (int j = 0; j < D1; ++j) s += Rm[i][j] * w2s[j * D2 + c];
        T2[i][c] = s;
    }
    __syncthreads();
    if (tid < D2 * D2) {
        int a = tid >> 3, c = tid & 7;
        float s = 0.f;
        #pragma unroll
        for (int i = 0; i < D1; ++i) s += w2s[i * D2 + a] * T2[i][c];
        A8[a][c] = s;
        V8[a][c] = (a == c) ? 1.f : 0.f;
    }
    __syncthreads();

    // ---------------- LogEig: 8x8 parallel cyclic Jacobi ----------------
    const int i8 = (tid >> 3) & 7, j8 = tid & 7;
    for (int sweep = 0; sweep < 10; ++sweep) {
        for (int r = 0; r < 7; ++r) {
            if (tid < 4) {
                int k = tid;
                int sa = (k == 0) ? 0 : ((k - 1 + r) % 7) + 1;
                int sb = ((6 - k + r) % 7) + 1;
                int p = sa < sb ? sa : sb;
                int q = sa < sb ? sb : sa;
                float app = A8[p][p], aqq = A8[q][q], apq = A8[p][q];
                float c, s;
                if (fabsf(apq) < 1e-12f) { c = 1.f; s = 0.f; }
                else {
                    float th = (aqq - app) / (2.f * apq);
                    float t = 1.f / (fabsf(th) + sqrtf(fmaf(th, th, 1.f)));
                    if (th < 0.f) t = -t;
                    c = rsqrtf(fmaf(t, t, 1.f)); s = t * c;
                }
                al[p] = c; be[p] = -s; pr[p] = q;
                al[q] = c; be[q] =  s; pr[q] = p;
            }
            __syncthreads();
            float aij = 0.f, apj = 0.f;
            if (tid < 64) { aij = A8[i8][j8]; apj = A8[pr[i8]][j8]; }
            __syncthreads();
            if (tid < 64) A8[i8][j8] = al[i8] * aij + be[i8] * apj;
            __syncthreads();
            float bij = 0.f, bip = 0.f, vij = 0.f, vip = 0.f;
            if (tid < 64) {
                bij = A8[i8][j8]; bip = A8[i8][pr[j8]];
                vij = V8[i8][j8]; vip = V8[i8][pr[j8]];
            }
            __syncthreads();
            if (tid < 64) {
                A8[i8][j8] = al[j8] * bij + be[j8] * bip;
                V8[i8][j8] = al[j8] * vij + be[j8] * vip;
            }
            __syncthreads();
        }
        float sq = 0.f;
        if (tid < 64 && i8 != j8) sq = A8[i8][j8] * A8[i8][j8];
        #pragma unroll
        for (int o = 16; o; o >>= 1) sq += __shfl_down_sync(0xffffffffu, sq, o);
        if ((tid & 31) == 0) redw[tid >> 5] = sq;
        __syncthreads();
        if (tid == 0) {
            float t = 0.f;
            #pragma unroll
            for (int w = 0; w < 8; ++w) t += redw[w];
            cflag = (t < 1e-11f) ? 1 : 0;
        }
        __syncthreads();
        if (cflag) break;
    }

    // ---------------- L = V8 log(D) V8^T, then linear head ----------------
    if (tid < D2) lg8[tid] = logf(fmaxf(A8[tid][tid], 1e-30f));
    __syncthreads();
    if (tid < 64) {
        float s = 0.f;
        #pragma unroll
        for (int k = 0; k < D2; ++k) s += V8[i8][k] * lg8[k] * V8[j8][k];
        Lf[i8 * D2 + j8] = s;
    }
    __syncthreads();
    if (tid < 3) {
        float s = bls[tid];
        #pragma unroll
        for (int k = 0; k < 64; ++k) s += Lf[k] * wls[tid * 64 + k];
        out[b * 3 + tid] = s;
    }
}

extern "C" void kernel_launch(void* const* d_in, const int* in_sizes, int n_in,
                              void* d_out, int out_size)
{
    const float* x    = (const float*)d_in[0];
    const float* W1   = (const float*)d_in[1];
    const float* W2   = (const float*)d_in[2];
    const float* Wlin = (const float*)d_in[3];
    const float* blin = (const float*)d_in[4];
    float* out = (float*)d_out;

    const int B = in_sizes[0] / TLEN;   // 8192
    radarnet_kernel<<<B, 256>>>(x, W1, W2, Wlin, blin, out);
}

// round 2
// speedup vs baseline: 2.0368x; 2.0368x over previous
#include <cuda_runtime.h>

// RadarNet, two-kernel version.
// K1: x(8192,512) -> sliding-window covariance C(20,20) -> S1 = W1^T C W1 (16x16) -> scratch
// K2: one warp per row: Gershgorin-certified ReEig skip (rare 16x16 Jacobi fallback),
//     S2 = W2^T S1r W2 (8x8), register/shuffle 8x8 Jacobi LogEig, linear head.

namespace {
constexpr int   TLEN = 512;
constexpr int   WINW = 20;
constexpr int   NW   = 493;
constexpr int   D1   = 16;
constexpr int   D2   = 8;
constexpr float REEPS = 1e-4f;
constexpr int   MAXB = 8192;
}

__device__ float g_S1[MAXB * 256];

// ---------------------------------------------------------------------------
// Kernel 1: covariance + S1
// ---------------------------------------------------------------------------
__global__ __launch_bounds__(256)
void radar_cov_kernel(const float* __restrict__ gx,
                      const float* __restrict__ gW1)
{
    __shared__ __align__(16) float xs[544];
    __shared__ float w1s[WINW * D1];
    __shared__ float Cm[WINW][WINW + 1];
    __shared__ float Tm[WINW][D1];
    __shared__ float lagw[4][21];
    __shared__ float lag[21];
    __shared__ float mw[WINW];

    const int tid = threadIdx.x;
    const int b   = blockIdx.x;

    xs[tid]       = gx[b * TLEN + tid];
    xs[256 + tid] = gx[b * TLEN + 256 + tid];
    if (tid < 32) xs[512 + tid] = 0.f;
    for (int i = tid; i < WINW * D1; i += 256) w1s[i] = gW1[i];
    __syncthreads();

    // lag sums: lag[d] = sum_{n<493} x[n]*x[n+d];  lag[20] = sum x[n]
    float acc[21];
    #pragma unroll
    for (int d = 0; d < 21; ++d) acc[d] = 0.f;
    if (tid < 124) {
        const float4* x4 = reinterpret_cast<const float4*>(xs);
        float xv[24];
        #pragma unroll
        for (int q = 0; q < 6; ++q) {
            float4 v = x4[tid + q];
            xv[4*q+0] = v.x; xv[4*q+1] = v.y; xv[4*q+2] = v.z; xv[4*q+3] = v.w;
        }
        #pragma unroll
        for (int k = 0; k < 4; ++k) {
            if (4 * tid + k <= NW - 1) {
                float xk = xv[k];
                #pragma unroll
                for (int d = 0; d < WINW; ++d) acc[d] = fmaf(xk, xv[k + d], acc[d]);
                acc[20] += xk;
            }
        }
    }
    if (tid < 128) {
        #pragma unroll
        for (int d = 0; d < 21; ++d) {
            float v = acc[d];
            #pragma unroll
            for (int o = 16; o; o >>= 1) v += __shfl_down_sync(0xffffffffu, v, o);
            if ((tid & 31) == 0) lagw[tid >> 5][d] = v;
        }
    }
    __syncthreads();

    // warp 0: combine partials + mean prefix scan
    if (tid < 32) {
        if (tid < 21) lag[tid] = lagw[0][tid] + lagw[1][tid] + lagw[2][tid] + lagw[3][tid];
        __syncwarp();
        float sum0 = lag[20];
        float val  = 0.f;
        if (tid >= 1 && tid < WINW) val = xs[NW - 1 + tid] - xs[tid - 1];
        #pragma unroll
        for (int o = 1; o < 32; o <<= 1) {
            float t = __shfl_up_sync(0xffffffffu, val, o);
            if (tid >= o) val += t;
        }
        if (tid < WINW) mw[tid] = (sum0 + val) * (1.f / (float)NW);
    }
    __syncthreads();

    // C entries: 210 threads, one (w,v) pair each.
    // S(w, v) = lag[v-w] + sum_{u=1..w} ( x[NW-1+u]x[NW-1+u+d] - x[u-1]x[u-1+d] )
    if (tid < 210) {
        int idx = tid;
        int w = (int)(20.5f - sqrtf(420.25f - 2.0f * (float)idx));
        while (20 * w - (w * (w - 1)) / 2 > idx) --w;
        while (20 * (w + 1) - ((w + 1) * w) / 2 <= idx) ++w;
        int v = w + (idx - (20 * w - (w * (w - 1)) / 2));
        int d = v - w;
        float s = lag[d];
        for (int u = 1; u <= w; ++u)
            s += xs[NW - 1 + u] * xs[NW - 1 + u + d] - xs[u - 1] * xs[u - 1 + d];
        float cv = (s - (float)NW * mw[w] * mw[v]) * (1.f / (float)(NW - 1));
        Cm[w][v] = cv; Cm[v][w] = cv;
    }
    __syncthreads();

    // Tm = C * W1
    for (int idx = tid; idx < WINW * D1; idx += 256) {
        int w = idx >> 4, j = idx & 15;
        float s = 0.f;
        #pragma unroll
        for (int v2 = 0; v2 < WINW; ++v2) s = fmaf(Cm[w][v2], w1s[v2 * D1 + j], s);
        Tm[w][j] = s;
    }
    __syncthreads();

    // S1 = W1^T * Tm  -> global scratch
    {
        int i16 = tid >> 4, j16 = tid & 15;
        float s = 0.f;
        #pragma unroll
        for (int w = 0; w < WINW; ++w) s = fmaf(w1s[w * D1 + i16], Tm[w][j16], s);
        g_S1[b * 256 + tid] = s;
    }
}

// ---------------------------------------------------------------------------
// Kernel 2: one warp per row: ReEig check / S2 / LogEig / head
// ---------------------------------------------------------------------------
__global__ __launch_bounds__(256)
void radar_eig_kernel(const float* __restrict__ gW2,
                      const float* __restrict__ gWl,
                      const float* __restrict__ gbl,
                      float* __restrict__ out, int B)
{
    __shared__ float w2s[D1 * D2];
    __shared__ float wls[3 * 64];
    __shared__ float bls[3];
    __shared__ float T2s[8][D1][D2];
    __shared__ float Vd[8][72];                  // V (64) + log-eig (8)
    __shared__ float al8[8][8], be8[8][8];
    __shared__ int   prr[8][8];
    // rare 16x16 fallback scratch
    __shared__ float sA[8][16][17], sV[8][16][17];
    __shared__ float al16[8][16], be16[8][16];
    __shared__ int   pr16[8][16];

    const int tid = threadIdx.x, wp = tid >> 5, l = tid & 31;
    const unsigned FULL = 0xffffffffu;

    if (tid < D1 * D2) w2s[tid] = gW2[tid];
    if (tid < 192)     wls[tid] = gWl[tid];
    if (tid < 3)       bls[tid] = gbl[tid];
    __syncthreads();

    const int row = blockIdx.x * 8 + wp;
    if (row >= B) return;                 // no __syncthreads below this point

    // lane l holds S1[r][hh*8 .. hh*8+7], r = l>>1, hh = l&1
    const int r = l >> 1, hh = l & 1;
    float s[8];
    {
        const float4* p = reinterpret_cast<const float4*>(g_S1 + row * 256 + r * 16 + hh * 8);
        float4 q0 = p[0], q1 = p[1];
        s[0]=q0.x; s[1]=q0.y; s[2]=q0.z; s[3]=q0.w;
        s[4]=q1.x; s[5]=q1.y; s[6]=q1.z; s[7]=q1.w;
    }

    // Gershgorin lower bound on lambda_min(S1)
    float rs = 0.f;
    #pragma unroll
    for (int k = 0; k < 8; ++k) { int c = hh * 8 + k; rs += (c == r) ? 0.f : fabsf(s[k]); }
    rs += __shfl_xor_sync(FULL, rs, 1);
    float dcand = s[r & 7];
    float dval  = __shfl_sync(FULL, dcand, r * 2 + (r >> 3));
    float bnd = dval - rs;
    #pragma unroll
    for (int o = 16; o; o >>= 1) bnd = fminf(bnd, __shfl_xor_sync(FULL, bnd, o));

    if (bnd < REEPS) {
        // rare path: 16x16 cyclic Jacobi in per-warp shared memory
        #pragma unroll
        for (int k = 0; k < 8; ++k) {
            sA[wp][r][hh*8+k] = s[k];
            sV[wp][r][hh*8+k] = (r == hh*8+k) ? 1.f : 0.f;
        }
        __syncwarp();
        for (int sweep = 0; sweep < 10; ++sweep) {
            for (int rr = 0; rr < 15; ++rr) {
                if (l < 8) {
                    int k  = l;
                    int sa = (k == 0) ? 0 : ((k - 1 + rr) % 15) + 1;
                    int sb = ((14 - k + rr) % 15) + 1;
                    int p = sa < sb ? sa : sb, q = sa < sb ? sb : sa;
                    float app = sA[wp][p][p], aqq = sA[wp][q][q], apq = sA[wp][p][q];
                    float c, sn;
                    if (fabsf(apq) < 1e-12f) { c = 1.f; sn = 0.f; }
                    else {
                        float th = __fdividef(aqq - app, 2.f * apq);
                        float t  = __fdividef(1.f, fabsf(th) + sqrtf(fmaf(th, th, 1.f)));
                        if (th < 0.f) t = -t;
                        c = rsqrtf(fmaf(t, t, 1.f)); sn = t * c;
                    }
                    al16[wp][p] = c; be16[wp][p] = -sn; pr16[wp][p] = q;
                    al16[wp][q] = c; be16[wp][q] =  sn; pr16[wp][q] = p;
                }
                __syncwarp();
                float cur[8], oth[8];
                {
                    int   pi = pr16[wp][r];
                    float ar = al16[wp][r], br = be16[wp][r];
                    #pragma unroll
                    for (int k = 0; k < 8; ++k) {
                        cur[k] = sA[wp][r][hh*8+k]; oth[k] = sA[wp][pi][hh*8+k];
                    }
                    __syncwarp();
                    #pragma unroll
                    for (int k = 0; k < 8; ++k) sA[wp][r][hh*8+k] = fmaf(ar, cur[k], br * oth[k]);
                }
                __syncwarp();
                #pragma unroll
                for (int k = 0; k < 8; ++k) {
                    int c = hh*8+k, pc = pr16[wp][c];
                    cur[k] = al16[wp][c] * sA[wp][r][c] + be16[wp][c] * sA[wp][r][pc];
                    oth[k] = al16[wp][c] * sV[wp][r][c] + be16[wp][c] * sV[wp][r][pc];
                }
                __syncwarp();
                #pragma unroll
                for (int k = 0; k < 8; ++k) { sA[wp][r][hh*8+k] = cur[k]; sV[wp][r][hh*8+k] = oth[k]; }
                __syncwarp();
            }
            float off = 0.f;
            #pragma unroll
            for (int k = 0; k < 8; ++k) {
                int c = hh*8+k;
                if (c != r) { float a = sA[wp][r][c]; off += a * a; }
            }
            #pragma unroll
            for (int o = 16; o; o >>= 1) off += __shfl_xor_sync(FULL, off, o);
            if (off < 1e-10f) break;
        }
        #pragma unroll
        for (int k = 0; k < 8; ++k) {
            int c = hh*8+k; float a = 0.f;
            #pragma unroll
            for (int t = 0; t < 16; ++t)
                a += sV[wp][r][t] * fmaxf(sA[wp][t][t], REEPS) * sV[wp][c][t];
            s[k] = a;
        }
        __syncwarp();
    }
    // else: S1r == S1 exactly (no eigenvalue can be below eps)

    // ---- S2 = W2^T S1r W2 ----
    float pt[8];
    #pragma unroll
    for (int c = 0; c < 8; ++c) {
        float a = 0.f;
        #pragma unroll
        for (int k = 0; k < 8; ++k) a = fmaf(s[k], w2s[(hh*8+k)*8 + c], a);
        pt[c] = a;
    }
    #pragma unroll
    for (int c = 0; c < 8; ++c) pt[c] += __shfl_xor_sync(FULL, pt[c], 1);
    if (hh == 0) {
        #pragma unroll
        for (int c = 0; c < 8; ++c) T2s[wp][r][c] = pt[c];
    }
    __syncwarp();

    const int i4 = l >> 3, j8 = l & 7;
    float a0 = 0.f, a1 = 0.f;
    #pragma unroll
    for (int i = 0; i < 16; ++i) {
        float t = T2s[wp][i][j8];
        a0 = fmaf(w2s[i*8 + i4],     t, a0);
        a1 = fmaf(w2s[i*8 + i4 + 4], t, a1);
    }
    float v0 = (i4 == j8) ? 1.f : 0.f;
    float v1 = (i4 + 4 == j8) ? 1.f : 0.f;

    // ---- LogEig: register/shuffle 8x8 cyclic Jacobi ----
    for (int sweep = 0; sweep < 10; ++sweep) {
        for (int rr = 0; rr < 7; ++rr) {
            int k  = l & 3;
            int sa = (k == 0) ? 0 : ((k - 1 + rr) % 7) + 1;
            int sb = ((6 - k + rr) % 7) + 1;
            int p = sa < sb ? sa : sb, q = sa < sb ? sb : sa;
            int srcpp = (p & 3) * 8 + p;
            int srcqq = (q & 3) * 8 + q;
            int srcpq = (p & 3) * 8 + q;
            float pp0 = __shfl_sync(FULL, a0, srcpp), pp1 = __shfl_sync(FULL, a1, srcpp);
            float qq0 = __shfl_sync(FULL, a0, srcqq), qq1 = __shfl_sync(FULL, a1, srcqq);
            float pq0 = __shfl_sync(FULL, a0, srcpq), pq1 = __shfl_sync(FULL, a1, srcpq);
            if (l < 4) {
                float app = (p >= 4) ? pp1 : pp0;
                float aqq = (q >= 4) ? qq1 : qq0;
                float apq = (p >= 4) ? pq1 : pq0;
                float c, sn;
                if (fabsf(apq) < 1e-12f) { c = 1.f; sn = 0.f; }
                else {
                    float th = __fdividef(aqq - app, 2.f * apq);
                    float t  = __fdividef(1.f, fabsf(th) + sqrtf(fmaf(th, th, 1.f)));
                    if (th < 0.f) t = -t;
                    c = rsqrtf(fmaf(t, t, 1.f)); sn = t * c;
                }
                al8[wp][p] = c; be8[wp][p] = -sn; prr[wp][p] = q;
                al8[wp][q] = c; be8[wp][q] =  sn; prr[wp][q] = p;
            }
            __syncwarp();
            // row update: A <- J^T A
            int   ra = i4, rb = i4 + 4;
            int   pa = prr[wp][ra], pb = prr[wp][rb];
            float ala = al8[wp][ra], bea = be8[wp][ra];
            float alb = al8[wp][rb], beb = be8[wp][rb];
            int   sa0 = (pa & 3) * 8 + j8, sb0 = (pb & 3) * 8 + j8;
            float u00 = __shfl_sync(FULL, a0, sa0), u01 = __shfl_sync(FULL, a1, sa0);
            float u10 = __shfl_sync(FULL, a0, sb0), u11 = __shfl_sync(FULL, a1, sb0);
            float xa = (pa >= 4) ? u01 : u00;
            float xb = (pb >= 4) ? u11 : u10;
            a0 = fmaf(ala, a0, bea * xa);
            a1 = fmaf(alb, a1, beb * xb);
            // column update: A <- A J, V <- V J
            int   pj = prr[wp][j8];
            float alj = al8[wp][j8], bej = be8[wp][j8];
            int   sc = (l & 24) + pj;
            float b0 = __shfl_sync(FULL, a0, sc), b1 = __shfl_sync(FULL, a1, sc);
            float w0 = __shfl_sync(FULL, v0, sc), w1 = __shfl_sync(FULL, v1, sc);
            a0 = fmaf(alj, a0, bej * b0); a1 = fmaf(alj, a1, bej * b1);
            v0 = fmaf(alj, v0, bej * w0); v1 = fmaf(alj, v1, bej * w1);
        }
        float off = ((i4 != j8) ? a0 * a0 : 0.f) + ((i4 + 4 != j8) ? a1 * a1 : 0.f);
        #pragma unroll
        for (int o = 16; o; o >>= 1) off += __shfl_xor_sync(FULL, off, o);
        if (off < 1e-11f) break;
    }

    // ---- L = V log(D) V^T, then head ----
    __syncwarp();
    if (j8 == i4)     Vd[wp][64 + i4]     = logf(fmaxf(a0, 1e-30f));
    if (j8 == i4 + 4) Vd[wp][64 + i4 + 4] = logf(fmaxf(a1, 1e-30f));
    Vd[wp][i4 * 8 + j8]       = v0;
    Vd[wp][(i4 + 4) * 8 + j8] = v1;
    __syncwarp();

    float L0 = 0.f, L1 = 0.f;
    #pragma unroll
    for (int k = 0; k < 8; ++k) {
        float lgv = Vd[wp][64 + k];
        float vjk = Vd[wp][j8 * 8 + k];
        L0 = fmaf(Vd[wp][i4 * 8 + k] * lgv,       vjk, L0);
        L1 = fmaf(Vd[wp][(i4 + 4) * 8 + k] * lgv, vjk, L1);
    }
    int f0 = i4 * 8 + j8, f1 = (i4 + 4) * 8 + j8;
    float o0 = L0 * wls[f0]       + L1 * wls[f1];
    float o1 = L0 * wls[64 + f0]  + L1 * wls[64 + f1];
    float o2 = L0 * wls[128 + f0] + L1 * wls[128 + f1];
    #pragma unroll
    for (int o = 16; o; o >>= 1) {
        o0 += __shfl_xor_sync(FULL, o0, o);
        o1 += __shfl_xor_sync(FULL, o1, o);
        o2 += __shfl_xor_sync(FULL, o2, o);
    }
    if (l == 0) {
        out[row * 3 + 0] = o0 + bls[0];
        out[row * 3 + 1] = o1 + bls[1];
        out[row * 3 + 2] = o2 + bls[2];
    }
}

extern "C" void kernel_launch(void* const* d_in, const int* in_sizes, int n_in,
                              void* d_out, int out_size)
{
    const float* x    = (const float*)d_in[0];
    const float* W1   = (const float*)d_in[1];
    const float* W2   = (const float*)d_in[2];
    const float* Wlin = (const float*)d_in[3];
    const float* blin = (const float*)d_in[4];
    float* out = (float*)d_out;

    const int B = in_sizes[0] / TLEN;     // 8192
    radar_cov_kernel<<<B, 256>>>(x, W1);
    radar_eig_kernel<<<(B + 7) / 8, 256>>>(W2, Wlin, blin, out, B);
}